// round 13
// baseline (speedup 1.0000x reference)
#include <cuda_runtime.h>
#include <cuda_fp16.h>

// CircularNN R12: S=64 samples/CTA, NT=1024 (32 warps), 1 CTA/SM.
// 32 sample-pairs, PADH2=785 (odd): gather bank = (17p + idx) mod 32 is a
// bijection over the 32 pairs -> every gather LDS.32 is exactly 1 wavefront
// and serves 64 samples. Packed records (prep kernel), HFMA2 taps, MUFU.TANH
// gelu, conflict-free FC. smem = 200,960 B (2 x 32 x 785 half2).

#define D      784
#define PADH2  785
#define S      64
#define NPAIR  32
#define NW     32
#define NT     1024
#define NCLS   10

typedef unsigned long long ull;

// ---- packed records (filled by prep kernel each launch) ----
__device__ uint4    g_r1[D];
__device__ uint4    g_r2a[D], g_r2b[D];
__device__ uint4    g_i3[D],  g_w3a[D], g_w3b[D];
__device__ unsigned g_b3[D];

__device__ __forceinline__ unsigned duph(float w) {
    unsigned s = __half_as_ushort(__float2half_rn(w));
    return s | (s << 16);
}
__device__ __forceinline__ __half2 u2h(unsigned u) {
    return *reinterpret_cast<const __half2*>(&u);
}

__global__ void prep_kernel(const int* __restrict__ idx1, const float* __restrict__ w1, const float* __restrict__ b1,
                            const int* __restrict__ idx2, const float* __restrict__ w2, const float* __restrict__ b2,
                            const int* __restrict__ idx3, const float* __restrict__ w3, const float* __restrict__ b3)
{
    int f = blockIdx.x * blockDim.x + threadIdx.x;
    if (f >= D) return;
    {
        unsigned i0 = (unsigned)idx1[2*f] * 4u, i1 = (unsigned)idx1[2*f+1] * 4u;
        uint4 r;
        r.x = i0 | (i1 << 16);
        r.y = duph(w1[2*f]);
        r.z = duph(w1[2*f+1]);
        r.w = duph(b1[f]);
        g_r1[f] = r;
    }
    {
        unsigned i0 = (unsigned)idx2[4*f]   * 4u, i1 = (unsigned)idx2[4*f+1] * 4u;
        unsigned i2 = (unsigned)idx2[4*f+2] * 4u, i3 = (unsigned)idx2[4*f+3] * 4u;
        uint4 a, b;
        a.x = i0 | (i1 << 16);
        a.y = i2 | (i3 << 16);
        a.z = duph(w2[4*f]);
        a.w = duph(w2[4*f+1]);
        b.x = duph(w2[4*f+2]);
        b.y = duph(w2[4*f+3]);
        b.z = duph(b2[f]);
        b.w = 0;
        g_r2a[f] = a;
        g_r2b[f] = b;
    }
    {
        unsigned i0 = (unsigned)idx3[8*f]   * 4u, i1 = (unsigned)idx3[8*f+1] * 4u;
        unsigned i2 = (unsigned)idx3[8*f+2] * 4u, i3 = (unsigned)idx3[8*f+3] * 4u;
        unsigned i4 = (unsigned)idx3[8*f+4] * 4u, i5 = (unsigned)idx3[8*f+5] * 4u;
        unsigned i6 = (unsigned)idx3[8*f+6] * 4u, i7 = (unsigned)idx3[8*f+7] * 4u;
        uint4 I, Wa, Wb;
        I.x = i0 | (i1 << 16);  I.y = i2 | (i3 << 16);
        I.z = i4 | (i5 << 16);  I.w = i6 | (i7 << 16);
        Wa.x = duph(w3[8*f]);   Wa.y = duph(w3[8*f+1]);
        Wa.z = duph(w3[8*f+2]); Wa.w = duph(w3[8*f+3]);
        Wb.x = duph(w3[8*f+4]); Wb.y = duph(w3[8*f+5]);
        Wb.z = duph(w3[8*f+6]); Wb.w = duph(w3[8*f+7]);
        g_i3[f] = I;  g_w3a[f] = Wa;  g_w3b[f] = Wb;
        g_b3[f] = duph(b3[f]);
    }
}

// ---- packed f32x2 helpers ----
__device__ __forceinline__ ull pack2(float a, float b) {
    ull r; asm("mov.b64 %0, {%1, %2};" : "=l"(r) : "f"(a), "f"(b)); return r;
}
__device__ __forceinline__ void unpack2(ull v, float& a, float& b) {
    asm("mov.b64 {%0, %1}, %2;" : "=f"(a), "=f"(b) : "l"(v));
}
#define FMA2(d,a,b,c) asm("fma.rn.f32x2 %0, %1, %2, %3;" : "=l"(d) : "l"(a), "l"(b), "l"(c))
#define MUL2(d,a,b)   asm("mul.rn.f32x2 %0, %1, %2;"     : "=l"(d) : "l"(a), "l"(b))

// tanh-form gelu via MUFU.TANH, packed fp32
__device__ __forceinline__ __half2 gelu2(float ax, float ay) {
    const ull C_A    = pack2(0.7978845608f, 0.7978845608f);
    const ull C_B    = pack2(0.0356774081f, 0.0356774081f);
    const ull C_HALF = pack2(0.5f, 0.5f);
    ull X = pack2(ax, ay);
    ull T; MUL2(T, X, X);
    ull V; FMA2(V, T, C_B, C_A);
    MUL2(V, V, X);
    float vx, vy; unpack2(V, vx, vy);
    float tx, ty;
    asm("tanh.approx.f32 %0, %1;" : "=f"(tx) : "f"(vx));
    asm("tanh.approx.f32 %0, %1;" : "=f"(ty) : "f"(vy));
    ull TH = pack2(tx, ty);
    ull XH; MUL2(XH, X, C_HALF);
    ull O;  FMA2(O, XH, TH, XH);
    float ox, oy; unpack2(O, ox, oy);
    return __floats2half2_rn(ox, oy);
}

#define LH2(off) (*(const __half2*)(sb + (off)))

extern __shared__ __align__(16) char smem_raw[];

__global__ __launch_bounds__(NT, 1)
void circnn_kernel(const float* __restrict__ x,
                   const float* __restrict__ fc_w, const float* __restrict__ fc_b,
                   float* __restrict__ out, int B)
{
    __half2* bufA = (__half2*)smem_raw;          // NPAIR*PADH2 half2 = 100,480 B
    __half2* bufB = bufA + NPAIR * PADH2;
    float*   part = (float*)smem_raw;            // alias bufA after layer3: 16*64*10 floats
    float*   lgts = part + 16 * S * NCLS;        // 64*10 floats

    const int tid  = threadIdx.x;
    const int lane = tid & 31;
    const int warp = tid >> 5;
    const long base = (long)blockIdx.x * S;

    // --- input: warp w owns sample pair w; coalesced loads, conflict-free STS.32 ---
    {
        const long s0 = base + 2 * warp;
        const float4* r0 = (const float4*)(x + s0 * (long)D);
        const float4* r1 = (const float4*)(x + (s0 + 1) * (long)D);
        unsigned* drow = (unsigned*)((char*)smem_raw + (warp * PADH2) * 4);
        for (int k = lane; k < D / 4; k += 32) {
            float4 a = __ldg(r0 + k);
            float4 b = __ldg(r1 + k);
            __half2 h0 = __floats2half2_rn(a.x, b.x);
            __half2 h1 = __floats2half2_rn(a.y, b.y);
            __half2 h2 = __floats2half2_rn(a.z, b.z);
            __half2 h3 = __floats2half2_rn(a.w, b.w);
            drow[4 * k + 0] = *(unsigned*)&h0;
            drow[4 * k + 1] = *(unsigned*)&h1;
            drow[4 * k + 2] = *(unsigned*)&h2;
            drow[4 * k + 3] = *(unsigned*)&h3;
        }
    }
    __syncthreads();

    // ---- layer 1 (K=2): warp owns feature f; 32 pairs per instruction ----
    {
        const char* sb = (const char*)(bufA + lane * PADH2);
        __half2*  dcol = bufB + lane * PADH2;
        #pragma unroll 4
        for (int f = warp; f < D; f += NW) {
            uint4 r = __ldg(g_r1 + f);
            __half2 acc = u2h(r.w);
            acc = __hfma2(u2h(r.y), LH2(r.x & 0xFFFFu), acc);
            acc = __hfma2(u2h(r.z), LH2(r.x >> 16), acc);
            float2 a = __half22float2(acc);
            dcol[f] = gelu2(a.x, a.y);
        }
    }
    __syncthreads();

    // ---- layer 2 (K=4) ----
    {
        const char* sb = (const char*)(bufB + lane * PADH2);
        __half2*  dcol = bufA + lane * PADH2;
        #pragma unroll 4
        for (int f = warp; f < D; f += NW) {
            uint4 A  = __ldg(&g_r2a[f]);
            uint4 Bv = __ldg(&g_r2b[f]);
            __half2 acc = u2h(Bv.z);
            __half2 t   = __hmul2(u2h(A.w),  LH2(A.x >> 16));
            acc = __hfma2(u2h(A.z),  LH2(A.x & 0xFFFFu), acc);
            t   = __hfma2(u2h(Bv.y), LH2(A.y >> 16), t);
            acc = __hfma2(u2h(Bv.x), LH2(A.y & 0xFFFFu), acc);
            acc = __hadd2(acc, t);
            float2 a = __half22float2(acc);
            dcol[f] = gelu2(a.x, a.y);
        }
    }
    __syncthreads();

    // ---- layer 3 (K=8): idx prefetch pipeline ----
    {
        const char* sb = (const char*)(bufA + lane * PADH2);
        __half2*  dcol = bufB + lane * PADH2;
        int f = warp;
        uint4 I = __ldg(&g_i3[f]);
        #pragma unroll 1
        for (; f < D; f += NW) {
            const int fn = (f + NW < D) ? (f + NW) : f;
            uint4 In = __ldg(&g_i3[fn]);           // prefetch next indices
            uint4 Wa = __ldg(&g_w3a[f]);
            uint4 Wb = __ldg(&g_w3b[f]);
            __half2 acc = u2h(__ldg(&g_b3[f]));
            __half2 t   = __hmul2(u2h(Wa.y), LH2(I.x >> 16));
            acc = __hfma2(u2h(Wa.x), LH2(I.x & 0xFFFFu), acc);
            t   = __hfma2(u2h(Wa.w), LH2(I.y >> 16), t);
            acc = __hfma2(u2h(Wa.z), LH2(I.y & 0xFFFFu), acc);
            t   = __hfma2(u2h(Wb.y), LH2(I.z >> 16), t);
            acc = __hfma2(u2h(Wb.x), LH2(I.z & 0xFFFFu), acc);
            t   = __hfma2(u2h(Wb.w), LH2(I.w >> 16), t);
            acc = __hfma2(u2h(Wb.z), LH2(I.w & 0xFFFFu), acc);
            acc = __hadd2(acc, t);
            float2 a = __half22float2(acc);
            dcol[f] = gelu2(a.x, a.y);
            I = In;
        }
    }
    __syncthreads();

    // --- FC partials: warpgroup-half hi = warp>>4 handles sample-half;
    //     lane = pair; chunk stride 16 within each half ---
    {
        const int wp = warp & 15;
        const int hi = warp >> 4;
        ull acc2[NCLS];
        #pragma unroll
        for (int c = 0; c < NCLS; ++c) acc2[c] = pack2(0.0f, 0.0f);

        const __half* hB = (const __half*)bufB;
        const __half* hrow = hB + lane * (PADH2 * 2) + hi;   // 17p-bank: conflict-free
        for (int c4 = wp; c4 < D / 4; c4 += 16) {
            const int f = c4 * 4;
            float h0 = __half2float(hrow[(f + 0) * 2]);
            float h1 = __half2float(hrow[(f + 1) * 2]);
            float h2 = __half2float(hrow[(f + 2) * 2]);
            float h3 = __half2float(hrow[(f + 3) * 2]);
            ull H01 = pack2(h0, h1);
            ull H23 = pack2(h2, h3);
            #pragma unroll
            for (int c = 0; c < NCLS; ++c) {
                float4 wv = __ldg((const float4*)(fc_w + c * D) + c4);
                ull W01 = pack2(wv.x, wv.y);
                ull W23 = pack2(wv.z, wv.w);
                FMA2(acc2[c], W01, H01, acc2[c]);
                FMA2(acc2[c], W23, H23, acc2[c]);
            }
        }
        // bufA dead after the layer-3 barrier -> part alias is safe
        const int s = 2 * lane + hi;                         // sample 0..63
        float* pp = part + (wp * S + s) * NCLS;
        #pragma unroll
        for (int c = 0; c < NCLS; ++c) {
            float lo, hv; unpack2(acc2[c], lo, hv);
            pp[c] = lo + hv;
        }
    }
    __syncthreads();

    // --- stage 1 reduction: 640 threads, one (sample, class) each ---
    if (tid < S * NCLS) {
        const int s = tid / NCLS;
        const int c = tid - s * NCLS;
        float sum = __ldg(fc_b + c);
        #pragma unroll
        for (int w = 0; w < 16; ++w)
            sum += part[(w * S + s) * NCLS + c];
        lgts[s * NCLS + c] = sum;
    }
    __syncthreads();

    // --- softmax: thread t handles sample t ---
    if (tid < S) {
        const long gs = base + tid;
        if (gs < B) {
            float l[NCLS];
            #pragma unroll
            for (int c = 0; c < NCLS; ++c) l[c] = lgts[tid * NCLS + c];
            float m = l[0];
            #pragma unroll
            for (int c = 1; c < NCLS; ++c) m = fmaxf(m, l[c]);
            float sum = 0.0f;
            #pragma unroll
            for (int c = 0; c < NCLS; ++c) { l[c] = __expf(l[c] - m); sum += l[c]; }
            const float inv = __fdividef(1.0f, sum);
            float* o = out + gs * NCLS;
            #pragma unroll
            for (int c = 0; c < NCLS; ++c) o[c] = l[c] * inv;
        }
    }
}

extern "C" void kernel_launch(void* const* d_in, const int* in_sizes, int n_in,
                              void* d_out, int out_size)
{
    const float* x    = (const float*)d_in[0];
    const int*   idx1 = (const int*)  d_in[1];
    const float* w1   = (const float*)d_in[2];
    const float* b1   = (const float*)d_in[3];
    const int*   idx2 = (const int*)  d_in[4];
    const float* w2   = (const float*)d_in[5];
    const float* b2   = (const float*)d_in[6];
    const int*   idx3 = (const int*)  d_in[7];
    const float* w3   = (const float*)d_in[8];
    const float* b3   = (const float*)d_in[9];
    const float* fc_w = (const float*)d_in[10];
    const float* fc_b = (const float*)d_in[11];
    float* out = (float*)d_out;

    const int B = in_sizes[0] / D;
    const int grid = (B + S - 1) / S;
    const int smem_bytes = 2 * NPAIR * PADH2 * (int)sizeof(__half2);  // 200,960

    prep_kernel<<<(D + 255) / 256, 256>>>(idx1, w1, b1, idx2, w2, b2, idx3, w3, b3);

    cudaFuncSetAttribute(circnn_kernel,
                         cudaFuncAttributeMaxDynamicSharedMemorySize, smem_bytes);

    circnn_kernel<<<grid, NT, smem_bytes>>>(x, fc_w, fc_b, out, B);
}

// round 14
// speedup vs baseline: 1.0575x; 1.0575x over previous
#include <cuda_runtime.h>
#include <cuda_fp16.h>

// CircularNN R13: R11 frame (S=32, NT=512, 2 CTAs/SM, PADH2=786, HFMA2 taps,
// MUFU.TANH gelu) + parity-matched feature pairing. Prep pairs an even-output
// feature (a even-parity taps) with an odd-output feature (K-a even-parity
// taps) and orders taps evens-first/odds-first so each gather instruction's
// two half-warps hit opposite-parity banks -> ~1.0 wavefront per gather LDS.
// Records indexed by slot; real output offset carried in the record.

#define D      784
#define PADH2  786
#define S      32
#define NPAIR  16
#define NW     16
#define NT     512
#define NCLS   10
#define NFP    392

typedef unsigned long long ull;

// ---- packed records (slot-indexed; filled by prep kernel each launch) ----
// g_r1[s]  = {j0|j1<<16, dup(w0), dup(w1), bias_u16|out<<16}
// g_r2a[s] = {j01, j23, dup(w0), dup(w1)}; g_r2b[s] = {dup(w2), dup(w3), dup(bias), out}
// g_i3[s]  = {j01,j23,j45,j67}; g_w3a/b = dup weights; g_b3[s] = bias_u16|out<<16
__device__ uint4    g_r1[D];
__device__ uint4    g_r2a[D], g_r2b[D];
__device__ uint4    g_i3[D],  g_w3a[D], g_w3b[D];
__device__ unsigned g_b3[D];

__device__ __forceinline__ unsigned duph(float w) {
    unsigned s = __half_as_ushort(__float2half_rn(w));
    return s | (s << 16);
}
__device__ __forceinline__ unsigned h16(float w) {
    return (unsigned)__half_as_ushort(__float2half_rn(w));
}
__device__ __forceinline__ __half2 u2h(unsigned u) {
    return *reinterpret_cast<const __half2*>(&u);
}

// ---- prep: single block, deterministic parity matching ----
__global__ void prep_kernel(const int* __restrict__ idx1, const float* __restrict__ w1, const float* __restrict__ b1,
                            const int* __restrict__ idx2, const float* __restrict__ w2, const float* __restrict__ b2,
                            const int* __restrict__ idx3, const float* __restrict__ w3, const float* __restrict__ b3)
{
    __shared__ unsigned char  sBucket[3][D];
    __shared__ unsigned short sRank[3][D];
    __shared__ int sCount[3][2][9];
    __shared__ int sM[3][9], sPB[3][9], sLB0[3][9], sLB1[3][9], sMtot[3];

    const int tid = threadIdx.x;
    const int f   = tid;
    const int Ks[3] = {2, 4, 8};
    const int* idxs[3] = {idx1, idx2, idx3};

    if (f < D) {
        #pragma unroll
        for (int l = 0; l < 3; ++l) {
            int K = Ks[l], a = 0;
            for (int t = 0; t < K; ++t) a += ((idxs[l][f * K + t] & 1) == 0);
            sBucket[l][f] = (unsigned char)a;
        }
    }
    __syncthreads();

    // deterministic ranks via warp ballot-scan; one (layer,cls,bucket) combo per warp
    {
        int warp = tid >> 5, lane = tid & 31;
        for (int combo = warp; combo < 54; combo += NT / 32) {
            int l = combo / 18, rem = combo % 18, cls = rem / 9, a = rem % 9;
            if (a <= Ks[l]) {
                int running = 0;
                for (int base = 0; base < D; base += 32) {
                    int ff = base + lane;
                    bool in = (ff < D) && ((ff & 1) == cls) && (sBucket[l][ff] == (unsigned char)a);
                    unsigned mask = __ballot_sync(0xffffffffu, in);
                    if (in) sRank[l][ff] = (unsigned short)(running + __popc(mask & ((1u << lane) - 1u)));
                    running += __popc(mask);
                }
                if (lane == 0) sCount[l][cls][a] = running;
            }
        }
    }
    __syncthreads();

    if (tid < 3) {
        int l = tid, K = Ks[l];
        int pb = 0, lb0 = 0, lb1 = 0;
        for (int a = 0; a <= K; ++a) {
            int m = min(sCount[l][0][a], sCount[l][1][K - a]);
            sM[l][a]  = m;
            sPB[l][a] = pb;  pb  += m;
            sLB0[l][a] = lb0; lb0 += sCount[l][0][a] - m;
        }
        sMtot[l] = pb;
        for (int b = 0; b <= K; ++b) {
            sLB1[l][b] = lb1; lb1 += sCount[l][1][b] - sM[l][K - b];
        }
    }
    __syncthreads();

    if (f >= D) return;
    const int cls = f & 1;

    #pragma unroll
    for (int l = 0; l < 3; ++l) {
        const int K = Ks[l];
        const int a = sBucket[l][f];
        const int r = sRank[l][f];
        int q;
        if (cls == 0) {
            int m = sM[l][a];
            q = (r < m) ? (sPB[l][a] + r) : (sMtot[l] + sLB0[l][a] + (r - m));
        } else {
            int m = sM[l][K - a];
            q = (r < m) ? (sPB[l][K - a] + r) : (sMtot[l] + sLB1[l][a] + (r - m));
        }
        const int slot = 2 * q + cls;

        // ordered taps: cls0 -> even-parity taps first; cls1 -> odd-parity first
        int ord[8];
        {
            int n = 0;
            int want = (cls == 0) ? 0 : 1;   // first pass parity (idx&1): even-parity tap = (idx&1)==0
            for (int pass = 0; pass < 2; ++pass) {
                for (int t = 0; t < K; ++t) {
                    int par = idxs[l][f * K + t] & 1;
                    if (par == ((pass == 0) ? want : (want ^ 1))) ord[n++] = t;
                }
            }
        }
        const unsigned outoff = (unsigned)(f * 4);

        if (l == 0) {
            unsigned j0 = (unsigned)idx1[2*f + ord[0]] * 4u;
            unsigned j1 = (unsigned)idx1[2*f + ord[1]] * 4u;
            uint4 rr;
            rr.x = j0 | (j1 << 16);
            rr.y = duph(w1[2*f + ord[0]]);
            rr.z = duph(w1[2*f + ord[1]]);
            rr.w = h16(b1[f]) | (outoff << 16);
            g_r1[slot] = rr;
        } else if (l == 1) {
            unsigned j[4];
            for (int t = 0; t < 4; ++t) j[t] = (unsigned)idx2[4*f + ord[t]] * 4u;
            uint4 A, Bv;
            A.x = j[0] | (j[1] << 16);
            A.y = j[2] | (j[3] << 16);
            A.z = duph(w2[4*f + ord[0]]);
            A.w = duph(w2[4*f + ord[1]]);
            Bv.x = duph(w2[4*f + ord[2]]);
            Bv.y = duph(w2[4*f + ord[3]]);
            Bv.z = duph(b2[f]);
            Bv.w = outoff;
            g_r2a[slot] = A;
            g_r2b[slot] = Bv;
        } else {
            unsigned j[8];
            for (int t = 0; t < 8; ++t) j[t] = (unsigned)idx3[8*f + ord[t]] * 4u;
            uint4 I, Wa, Wb;
            I.x = j[0] | (j[1] << 16);  I.y = j[2] | (j[3] << 16);
            I.z = j[4] | (j[5] << 16);  I.w = j[6] | (j[7] << 16);
            Wa.x = duph(w3[8*f + ord[0]]); Wa.y = duph(w3[8*f + ord[1]]);
            Wa.z = duph(w3[8*f + ord[2]]); Wa.w = duph(w3[8*f + ord[3]]);
            Wb.x = duph(w3[8*f + ord[4]]); Wb.y = duph(w3[8*f + ord[5]]);
            Wb.z = duph(w3[8*f + ord[6]]); Wb.w = duph(w3[8*f + ord[7]]);
            g_i3[slot] = I;  g_w3a[slot] = Wa;  g_w3b[slot] = Wb;
            g_b3[slot] = h16(b3[f]) | (outoff << 16);
        }
    }
}

// ---- packed f32x2 helpers ----
__device__ __forceinline__ ull pack2(float a, float b) {
    ull r; asm("mov.b64 %0, {%1, %2};" : "=l"(r) : "f"(a), "f"(b)); return r;
}
__device__ __forceinline__ void unpack2(ull v, float& a, float& b) {
    asm("mov.b64 {%0, %1}, %2;" : "=f"(a), "=f"(b) : "l"(v));
}
#define FMA2(d,a,b,c) asm("fma.rn.f32x2 %0, %1, %2, %3;" : "=l"(d) : "l"(a), "l"(b), "l"(c))
#define MUL2(d,a,b)   asm("mul.rn.f32x2 %0, %1, %2;"     : "=l"(d) : "l"(a), "l"(b))

// tanh-form gelu via MUFU.TANH, packed fp32
__device__ __forceinline__ __half2 gelu2(float ax, float ay) {
    const ull C_A    = pack2(0.7978845608f, 0.7978845608f);
    const ull C_B    = pack2(0.0356774081f, 0.0356774081f);
    const ull C_HALF = pack2(0.5f, 0.5f);
    ull X = pack2(ax, ay);
    ull T; MUL2(T, X, X);
    ull V; FMA2(V, T, C_B, C_A);
    MUL2(V, V, X);
    float vx, vy; unpack2(V, vx, vy);
    float tx, ty;
    asm("tanh.approx.f32 %0, %1;" : "=f"(tx) : "f"(vx));
    asm("tanh.approx.f32 %0, %1;" : "=f"(ty) : "f"(vy));
    ull TH = pack2(tx, ty);
    ull XH; MUL2(XH, X, C_HALF);
    ull O;  FMA2(O, XH, TH, XH);
    float ox, oy; unpack2(O, ox, oy);
    return __floats2half2_rn(ox, oy);
}

#define LH2(off) (*(const __half2*)(sb + (off)))

extern __shared__ __align__(16) char smem_raw[];

__global__ __launch_bounds__(NT, 2)
void circnn_kernel(const float* __restrict__ x,
                   const float* __restrict__ fc_w, const float* __restrict__ fc_b,
                   float* __restrict__ out, int B)
{
    __half2* bufA = (__half2*)smem_raw;          // NPAIR*PADH2 half2 = 50,304 B
    __half2* bufB = bufA + NPAIR * PADH2;
    float*   part = (float*)smem_raw;            // alias bufA after layer3
    float*   lgts = part + NW * S * NCLS;

    const int tid  = threadIdx.x;
    const int lane = tid & 31;
    const int warp = tid >> 5;
    const int p    = lane & 15;
    const int fo   = lane >> 4;
    const long base = (long)blockIdx.x * S;

    // --- input: warp w owns sample pair w ---
    {
        const long s0 = base + 2 * warp;
        const float4* r0 = (const float4*)(x + s0 * (long)D);
        const float4* r1 = (const float4*)(x + (s0 + 1) * (long)D);
        unsigned* drow = (unsigned*)((char*)smem_raw + (warp * PADH2) * 4);
        for (int k = lane; k < D / 4; k += 32) {
            float4 a = __ldg(r0 + k);
            float4 b = __ldg(r1 + k);
            __half2 h0 = __floats2half2_rn(a.x, b.x);
            __half2 h1 = __floats2half2_rn(a.y, b.y);
            __half2 h2 = __floats2half2_rn(a.z, b.z);
            __half2 h3 = __floats2half2_rn(a.w, b.w);
            drow[4 * k + 0] = *(unsigned*)&h0;
            drow[4 * k + 1] = *(unsigned*)&h1;
            drow[4 * k + 2] = *(unsigned*)&h2;
            drow[4 * k + 3] = *(unsigned*)&h3;
        }
    }
    __syncthreads();

    // ---- layer 1 (K=2): parity-matched slots ----
    {
        const char* sb = (const char*)(bufA + p * PADH2);
        char*       db = (char*)(bufB + p * PADH2);
        #pragma unroll 4
        for (int pb = warp; pb < NFP; pb += NW) {
            const int slot = 2 * pb + fo;
            uint4 r = __ldg(g_r1 + slot);
            __half2 acc = __half2half2(__ushort_as_half((unsigned short)(r.w & 0xFFFFu)));
            acc = __hfma2(u2h(r.y), LH2(r.x & 0xFFFFu), acc);
            acc = __hfma2(u2h(r.z), LH2(r.x >> 16), acc);
            float2 a = __half22float2(acc);
            *(__half2*)(db + (r.w >> 16)) = gelu2(a.x, a.y);
        }
    }
    __syncthreads();

    // ---- layer 2 (K=4) ----
    {
        const char* sb = (const char*)(bufB + p * PADH2);
        char*       db = (char*)(bufA + p * PADH2);
        #pragma unroll 4
        for (int pb = warp; pb < NFP; pb += NW) {
            const int slot = 2 * pb + fo;
            uint4 A  = __ldg(&g_r2a[slot]);
            uint4 Bv = __ldg(&g_r2b[slot]);
            __half2 acc = u2h(Bv.z);
            __half2 t   = __hmul2(u2h(A.w),  LH2(A.x >> 16));
            acc = __hfma2(u2h(A.z),  LH2(A.x & 0xFFFFu), acc);
            t   = __hfma2(u2h(Bv.y), LH2(A.y >> 16), t);
            acc = __hfma2(u2h(Bv.x), LH2(A.y & 0xFFFFu), acc);
            acc = __hadd2(acc, t);
            float2 a = __half22float2(acc);
            *(__half2*)(db + Bv.w) = gelu2(a.x, a.y);
        }
    }
    __syncthreads();

    // ---- layer 3 (K=8): idx prefetch pipeline ----
    {
        const char* sb = (const char*)(bufA + p * PADH2);
        char*       db = (char*)(bufB + p * PADH2);
        int pb = warp;
        uint4 I = __ldg(&g_i3[2 * pb + fo]);
        #pragma unroll 1
        for (; pb < NFP; pb += NW) {
            const int slot = 2 * pb + fo;
            const int pn = pb + NW;
            const int sn = (pn < NFP) ? (2 * pn + fo) : slot;
            uint4 In = __ldg(&g_i3[sn]);           // prefetch next indices
            uint4 Wa = __ldg(&g_w3a[slot]);
            uint4 Wb = __ldg(&g_w3b[slot]);
            unsigned bo = __ldg(&g_b3[slot]);
            __half2 acc = __half2half2(__ushort_as_half((unsigned short)(bo & 0xFFFFu)));
            __half2 t   = __hmul2(u2h(Wa.y), LH2(I.x >> 16));
            acc = __hfma2(u2h(Wa.x), LH2(I.x & 0xFFFFu), acc);
            t   = __hfma2(u2h(Wa.w), LH2(I.y >> 16), t);
            acc = __hfma2(u2h(Wa.z), LH2(I.y & 0xFFFFu), acc);
            t   = __hfma2(u2h(Wb.y), LH2(I.z >> 16), t);
            acc = __hfma2(u2h(Wb.x), LH2(I.z & 0xFFFFu), acc);
            t   = __hfma2(u2h(Wb.w), LH2(I.w >> 16), t);
            acc = __hfma2(u2h(Wb.z), LH2(I.w & 0xFFFFu), acc);
            acc = __hadd2(acc, t);
            float2 a = __half22float2(acc);
            *(__half2*)(db + (bo >> 16)) = gelu2(a.x, a.y);
            I = In;
        }
    }
    __syncthreads();

    // --- FC partials: lane = sample; feature-packed f32x2 FMAs ---
    {
        ull acc2[NCLS];
        #pragma unroll
        for (int c = 0; c < NCLS; ++c) acc2[c] = pack2(0.0f, 0.0f);

        const __half* hB = (const __half*)bufB;
        const int sp = lane >> 1, hi = lane & 1;
        const __half* hrow = hB + sp * (PADH2 * 2) + hi;
        for (int c4 = warp; c4 < D / 4; c4 += NW) {
            const int f = c4 * 4;
            float h0 = __half2float(hrow[(f + 0) * 2]);
            float h1 = __half2float(hrow[(f + 1) * 2]);
            float h2 = __half2float(hrow[(f + 2) * 2]);
            float h3 = __half2float(hrow[(f + 3) * 2]);
            ull H01 = pack2(h0, h1);
            ull H23 = pack2(h2, h3);
            #pragma unroll
            for (int c = 0; c < NCLS; ++c) {
                float4 wv = __ldg((const float4*)(fc_w + c * D) + c4);
                ull W01 = pack2(wv.x, wv.y);
                ull W23 = pack2(wv.z, wv.w);
                FMA2(acc2[c], W01, H01, acc2[c]);
                FMA2(acc2[c], W23, H23, acc2[c]);
            }
        }
        __syncthreads();   // bufA dead for everyone -> alias as part
        float* pp = part + (warp * S + lane) * NCLS;
        #pragma unroll
        for (int c = 0; c < NCLS; ++c) {
            float lo, hv; unpack2(acc2[c], lo, hv);
            pp[c] = lo + hv;
        }
    }
    __syncthreads();

    // --- stage 1 reduction: 320 threads, one (sample, class) each ---
    if (tid < S * NCLS) {
        const int s = tid / NCLS;
        const int c = tid - s * NCLS;
        float sum = __ldg(fc_b + c);
        #pragma unroll
        for (int w = 0; w < NW; ++w)
            sum += part[(w * S + s) * NCLS + c];
        lgts[s * NCLS + c] = sum;
    }
    __syncthreads();

    // --- softmax: thread t handles sample t ---
    if (tid < S) {
        const long gs = base + tid;
        if (gs < B) {
            float l[NCLS];
            #pragma unroll
            for (int c = 0; c < NCLS; ++c) l[c] = lgts[tid * NCLS + c];
            float m = l[0];
            #pragma unroll
            for (int c = 1; c < NCLS; ++c) m = fmaxf(m, l[c]);
            float sum = 0.0f;
            #pragma unroll
            for (int c = 0; c < NCLS; ++c) { l[c] = __expf(l[c] - m); sum += l[c]; }
            const float inv = __fdividef(1.0f, sum);
            float* o = out + gs * NCLS;
            #pragma unroll
            for (int c = 0; c < NCLS; ++c) o[c] = l[c] * inv;
        }
    }
}

extern "C" void kernel_launch(void* const* d_in, const int* in_sizes, int n_in,
                              void* d_out, int out_size)
{
    const float* x    = (const float*)d_in[0];
    const int*   idx1 = (const int*)  d_in[1];
    const float* w1   = (const float*)d_in[2];
    const float* b1   = (const float*)d_in[3];
    const int*   idx2 = (const int*)  d_in[4];
    const float* w2   = (const float*)d_in[5];
    const float* b2   = (const float*)d_in[6];
    const int*   idx3 = (const int*)  d_in[7];
    const float* w3   = (const float*)d_in[8];
    const float* b3   = (const float*)d_in[9];
    const float* fc_w = (const float*)d_in[10];
    const float* fc_b = (const float*)d_in[11];
    float* out = (float*)d_out;

    const int B = in_sizes[0] / D;
    const int grid = (B + S - 1) / S;
    const int smem_bytes = 2 * NPAIR * PADH2 * (int)sizeof(__half2);  // 100,608

    prep_kernel<<<1, 1024>>>(idx1, w1, b1, idx2, w2, b2, idx3, w3, b3);

    cudaFuncSetAttribute(circnn_kernel,
                         cudaFuncAttributeMaxDynamicSharedMemorySize, smem_bytes);

    circnn_kernel<<<grid, NT, smem_bytes>>>(x, fc_w, fc_b, out, B);
}